// round 15
// baseline (speedup 1.0000x reference)
#include <cuda_runtime.h>
#include <cuda_fp16.h>
#include <cstdint>

#define T_TOK 32768
#define H_DIM 2048
#define I_DIM 768

// ---------------- static device scratch (fp16) ------------------------------
__device__ __half g_Ah[(size_t)T_TOK * H_DIM];          // hidden   [T,H]
__device__ __half g_Wgu[(size_t)2 * I_DIM * H_DIM];     // w_gate_up^T [2I,H]
__device__ __half g_Wd[(size_t)H_DIM * I_DIM];          // w_down^T    [H,I]
__device__ __half g_X[(size_t)T_TOK * I_DIM];           // silu(g)*u   [T,I]

// ---------------- helpers ----------------------------------------------------
__device__ __forceinline__ uint32_t smem_u32(const void* p) {
    return (uint32_t)__cvta_generic_to_shared(p);
}
__device__ __forceinline__ void cp16(uint32_t dst, const void* src) {
    asm volatile("cp.async.cg.shared.global [%0], [%1], 16;" :: "r"(dst), "l"(src));
}
__device__ __forceinline__ void cp_commit() {
    asm volatile("cp.async.commit_group;" ::: "memory");
}
template <int N>
__device__ __forceinline__ void cp_wait() {
    asm volatile("cp.async.wait_group %0;" :: "n"(N) : "memory");
}
__device__ __forceinline__ void ldsm_x4(uint32_t* r, uint32_t addr) {
    asm volatile("ldmatrix.sync.aligned.m8n8.x4.shared.b16 {%0,%1,%2,%3}, [%4];"
                 : "=r"(r[0]), "=r"(r[1]), "=r"(r[2]), "=r"(r[3]) : "r"(addr));
}
__device__ __forceinline__ void mma16816(float* d, const uint32_t* a,
                                         uint32_t b0, uint32_t b1) {
    asm volatile(
        "mma.sync.aligned.m16n8k16.row.col.f32.f16.f16.f32 "
        "{%0,%1,%2,%3}, {%4,%5,%6,%7}, {%8,%9}, {%0,%1,%2,%3};"
        : "+f"(d[0]), "+f"(d[1]), "+f"(d[2]), "+f"(d[3])
        : "r"(a[0]), "r"(a[1]), "r"(a[2]), "r"(a[3]), "r"(b0), "r"(b1));
}
__device__ __forceinline__ uint32_t pk2h(float a, float b) {
    __half2 t = __floats2half2_rn(a, b);
    return *reinterpret_cast<uint32_t*>(&t);
}

// SMEM stage: rows of 32 fp16 = 64B data + 16B pad -> stride 80B (20 words).
//   A tile (128 rows) @0, B tile (128 rows) @10240
#define ROWB        80
#define B_OFF       10240
#define STAGE_BYTES 20480
#define NSTAGE      5
#define PFD         3
#define SMEM_BYTES  (NSTAGE * STAGE_BYTES)

// load one ks-block of fragments (A: 4 x ldsm.x4, B: 4 x ldsm.x4)
__device__ __forceinline__ void load_frags(
    uint32_t SB, int ks, int warp_m, int warp_n,
    int arow, int acol, int brow, int bcol,
    uint32_t af[4][4], uint32_t bf[16])
{
#pragma unroll
    for (int bq = 0; bq < 4; bq++) {
        uint32_t rb = SB + B_OFF + (warp_n * 64 + bq * 16 + brow) * ROWB
                    + ks * 32 + bcol;
        ldsm_x4(&bf[bq * 4], rb);
    }
#pragma unroll
    for (int mi = 0; mi < 4; mi++) {
        uint32_t ra = SB + (warp_m * 64 + mi * 16 + arow) * ROWB + ks * 32 + acol;
        ldsm_x4(af[mi], ra);
    }
}

// ============================================================================
// GEMM1: hidden[T,H] x Wgu^T[2I,H] -> silu(gate)*up -> X[T,I] fp16
// CTA: 128 thr, 4 warps (2m x 2n). Tile 128x64(g+u). Warp tile 64x64.
// Pair-unrolled mainloop: ONE barrier per 2 K-iterations.
// ============================================================================
__device__ __forceinline__ void g1_load_stage(
    uint32_t SB, int k0, int bm, int nt,
    const __half* __restrict__ A, const __half* __restrict__ W, int tid)
{
#pragma unroll
    for (int c = tid; c < 512; c += 128) {            // A: 128 rows x 4 x 16B
        int row = c >> 2, kc = c & 3;
        cp16(SB + row * ROWB + kc * 16,
             A + (size_t)(bm + row) * H_DIM + k0 + kc * 8);
    }
#pragma unroll
    for (int c = tid; c < 512; c += 128) {            // B: interleaved gate/up
        int row = c >> 2, kc = c & 3;
        int wn = row >> 6, r = row & 63;
        int gr = (r < 32) ? (nt * 64 + wn * 32 + r)
                          : (I_DIM + nt * 64 + wn * 32 + r - 32);
        cp16(SB + B_OFF + row * ROWB + kc * 16,
             W + (size_t)gr * H_DIM + k0 + kc * 8);
    }
}

__global__ __launch_bounds__(128, 2)
void gemm1_k(const __half* __restrict__ A, const __half* __restrict__ W,
             __half* __restrict__ X)
{
    extern __shared__ char smem[];
    const uint32_t sb = smem_u32(smem);
    const int tid = threadIdx.x, wid = tid >> 5, lane = tid & 31;
    const int warp_m = wid & 1, warp_n = wid >> 1;
    const int nt = blockIdx.x;                  // 0..11
    const int bm = blockIdx.y * 128;
    const int NITER = H_DIM / 32;               // 64 (even)

    float acc[4][8][4];                         // ni 0..3 gate, 4..7 up
#pragma unroll
    for (int mi = 0; mi < 4; mi++)
#pragma unroll
        for (int ni = 0; ni < 8; ni++)
#pragma unroll
            for (int v = 0; v < 4; v++) acc[mi][ni][v] = 0.f;

#pragma unroll
    for (int p = 0; p < PFD; p++) {
        g1_load_stage(sb + p * STAGE_BYTES, p * 32, bm, nt, A, W, tid);
        cp_commit();
    }

    const int arow = lane & 15;
    const int acol = (lane >> 4) * 16;
    const int brow = (lane & 7) + ((lane >> 4) << 3);
    const int bcol = ((lane >> 3) & 1) * 16;

    uint32_t afA[4][4], bfA[16], afB[4][4], bfB[16];

    cp_wait<1>();           // stages 0,1 complete
    __syncthreads();
    load_frags(sb, 0, warp_m, warp_n, arow, acol, brow, bcol, afA, bfA);

    int s0 = 0;             // stage of iteration `it` (pairs: it even)
    for (int it = 0; it < NITER; it += 2) {
        const int s1 = (s0 + 1 < NSTAGE) ? s0 + 1 : s0 + 1 - NSTAGE;
        const int s2 = (s0 + 2 < NSTAGE) ? s0 + 2 : s0 + 2 - NSTAGE;
        const int w0 = (s0 + 3 < NSTAGE) ? s0 + 3 : s0 + 3 - NSTAGE;
        const int w1 = (s0 + 4 < NSTAGE) ? s0 + 4 : s0 + 4 - NSTAGE;
        const uint32_t SB0 = sb + s0 * STAGE_BYTES;
        const uint32_t SB1 = sb + s1 * STAGE_BYTES;
        const uint32_t SB2 = sb + s2 * STAGE_BYTES;

        // prefetch 2 stages (targets last read 2 iters ago, pre-barrier)
        if (it + 3 < NITER)
            g1_load_stage(sb + w0 * STAGE_BYTES, (it + 3) * 32, bm, nt, A, W, tid);
        cp_commit();
        if (it + 4 < NITER)
            g1_load_stage(sb + w1 * STAGE_BYTES, (it + 4) * 32, bm, nt, A, W, tid);
        cp_commit();

        // ks1 of it (stage s0)
        load_frags(SB0, 1, warp_m, warp_n, arow, acol, brow, bcol, afB, bfB);
        // MMA ks0 of it (bufA)
#pragma unroll
        for (int mi = 0; mi < 4; mi++)
#pragma unroll
            for (int ni = 0; ni < 8; ni++)
                mma16816(acc[mi][ni], afA[mi], bfA[ni * 2], bfA[ni * 2 + 1]);

        // ks0 of it+1 (stage s1, visible since previous barrier)
        load_frags(SB1, 0, warp_m, warp_n, arow, acol, brow, bcol, afA, bfA);
        // MMA ks1 of it (bufB)
#pragma unroll
        for (int mi = 0; mi < 4; mi++)
#pragma unroll
            for (int ni = 0; ni < 8; ni++)
                mma16816(acc[mi][ni], afB[mi], bfB[ni * 2], bfB[ni * 2 + 1]);

        // ks1 of it+1 (stage s1)
        load_frags(SB1, 1, warp_m, warp_n, arow, acol, brow, bcol, afB, bfB);
        // MMA ks0 of it+1 (bufA)
#pragma unroll
        for (int mi = 0; mi < 4; mi++)
#pragma unroll
            for (int ni = 0; ni < 8; ni++)
                mma16816(acc[mi][ni], afA[mi], bfA[ni * 2], bfA[ni * 2 + 1]);

        // stage s2 complete + visible to all threads
        cp_wait<1>();
        __syncthreads();
        if (it + 2 < NITER)
            load_frags(SB2, 0, warp_m, warp_n, arow, acol, brow, bcol, afA, bfA);

        // MMA ks1 of it+1 (bufB)
#pragma unroll
        for (int mi = 0; mi < 4; mi++)
#pragma unroll
            for (int ni = 0; ni < 8; ni++)
                mma16816(acc[mi][ni], afB[mi], bfB[ni * 2], bfB[ni * 2 + 1]);

        s0 = s2;
    }

    // epilogue: silu(gate)*up -> fp16 X (gate=acc[ni], up=acc[ni+4])
    const int g = lane >> 2, t = lane & 3;
#pragma unroll
    for (int mi = 0; mi < 4; mi++)
#pragma unroll
        for (int ni = 0; ni < 4; ni++) {
            int col = nt * 64 + warp_n * 32 + ni * 8 + t * 2;
            int row0 = bm + warp_m * 64 + mi * 16 + g;
#pragma unroll
            for (int h = 0; h < 2; h++) {
                int row = row0 + h * 8;
                float g0 = acc[mi][ni][h*2],     g1 = acc[mi][ni][h*2+1];
                float u0 = acc[mi][ni+4][h*2],   u1 = acc[mi][ni+4][h*2+1];
                float x0 = u0 * g0 / (1.0f + __expf(-g0));
                float x1 = u1 * g1 / (1.0f + __expf(-g1));
                *reinterpret_cast<uint32_t*>(X + (size_t)row * I_DIM + col) = pk2h(x0, x1);
            }
        }
}

// ============================================================================
// GEMM2: X[T,I] x Wd^T[H,I] -> out[T,H] fp32
// CTA: 128 thr, 4 warps (2m x 2n). Tile 128x128. Warp tile 64x64.
// ============================================================================
__device__ __forceinline__ void g2_load_stage(
    uint32_t SB, int k0, int bm, int bn,
    const __half* __restrict__ X, const __half* __restrict__ D, int tid)
{
#pragma unroll
    for (int c = tid; c < 512; c += 128) {
        int row = c >> 2, kc = c & 3;
        cp16(SB + row * ROWB + kc * 16,
             X + (size_t)(bm + row) * I_DIM + k0 + kc * 8);
    }
#pragma unroll
    for (int c = tid; c < 512; c += 128) {
        int row = c >> 2, kc = c & 3;
        cp16(SB + B_OFF + row * ROWB + kc * 16,
             D + (size_t)(bn + row) * I_DIM + k0 + kc * 8);
    }
}

__global__ __launch_bounds__(128, 2)
void gemm2_k(const __half* __restrict__ X, const __half* __restrict__ D,
             float* __restrict__ out)
{
    extern __shared__ char smem[];
    const uint32_t sb = smem_u32(smem);
    const int tid = threadIdx.x, wid = tid >> 5, lane = tid & 31;
    const int warp_m = wid & 1, warp_n = wid >> 1;
    const int bn = blockIdx.x * 128;
    const int bm = blockIdx.y * 128;
    const int NITER = I_DIM / 32;               // 24 (even)

    float acc[4][8][4];
#pragma unroll
    for (int mi = 0; mi < 4; mi++)
#pragma unroll
        for (int ni = 0; ni < 8; ni++)
#pragma unroll
            for (int v = 0; v < 4; v++) acc[mi][ni][v] = 0.f;

#pragma unroll
    for (int p = 0; p < PFD; p++) {
        g2_load_stage(sb + p * STAGE_BYTES, p * 32, bm, bn, X, D, tid);
        cp_commit();
    }

    const int arow = lane & 15;
    const int acol = (lane >> 4) * 16;
    const int brow = (lane & 7) + ((lane >> 4) << 3);
    const int bcol = ((lane >> 3) & 1) * 16;

    uint32_t afA[4][4], bfA[16], afB[4][4], bfB[16];

    cp_wait<1>();
    __syncthreads();
    load_frags(sb, 0, warp_m, warp_n, arow, acol, brow, bcol, afA, bfA);

    int s0 = 0;
    for (int it = 0; it < NITER; it += 2) {
        const int s1 = (s0 + 1 < NSTAGE) ? s0 + 1 : s0 + 1 - NSTAGE;
        const int s2 = (s0 + 2 < NSTAGE) ? s0 + 2 : s0 + 2 - NSTAGE;
        const int w0 = (s0 + 3 < NSTAGE) ? s0 + 3 : s0 + 3 - NSTAGE;
        const int w1 = (s0 + 4 < NSTAGE) ? s0 + 4 : s0 + 4 - NSTAGE;
        const uint32_t SB0 = sb + s0 * STAGE_BYTES;
        const uint32_t SB1 = sb + s1 * STAGE_BYTES;
        const uint32_t SB2 = sb + s2 * STAGE_BYTES;

        if (it + 3 < NITER)
            g2_load_stage(sb + w0 * STAGE_BYTES, (it + 3) * 32, bm, bn, X, D, tid);
        cp_commit();
        if (it + 4 < NITER)
            g2_load_stage(sb + w1 * STAGE_BYTES, (it + 4) * 32, bm, bn, X, D, tid);
        cp_commit();

        load_frags(SB0, 1, warp_m, warp_n, arow, acol, brow, bcol, afB, bfB);
#pragma unroll
        for (int mi = 0; mi < 4; mi++)
#pragma unroll
            for (int ni = 0; ni < 8; ni++)
                mma16816(acc[mi][ni], afA[mi], bfA[ni * 2], bfA[ni * 2 + 1]);

        load_frags(SB1, 0, warp_m, warp_n, arow, acol, brow, bcol, afA, bfA);
#pragma unroll
        for (int mi = 0; mi < 4; mi++)
#pragma unroll
            for (int ni = 0; ni < 8; ni++)
                mma16816(acc[mi][ni], afB[mi], bfB[ni * 2], bfB[ni * 2 + 1]);

        load_frags(SB1, 1, warp_m, warp_n, arow, acol, brow, bcol, afB, bfB);
#pragma unroll
        for (int mi = 0; mi < 4; mi++)
#pragma unroll
            for (int ni = 0; ni < 8; ni++)
                mma16816(acc[mi][ni], afA[mi], bfA[ni * 2], bfA[ni * 2 + 1]);

        cp_wait<1>();
        __syncthreads();
        if (it + 2 < NITER)
            load_frags(SB2, 0, warp_m, warp_n, arow, acol, brow, bcol, afA, bfA);

#pragma unroll
        for (int mi = 0; mi < 4; mi++)
#pragma unroll
            for (int ni = 0; ni < 8; ni++)
                mma16816(acc[mi][ni], afB[mi], bfB[ni * 2], bfB[ni * 2 + 1]);

        s0 = s2;
    }

    const int g = lane >> 2, t = lane & 3;
#pragma unroll
    for (int mi = 0; mi < 4; mi++)
#pragma unroll
        for (int ni = 0; ni < 8; ni++) {
            int col = bn + warp_n * 64 + ni * 8 + t * 2;
            int row0 = bm + warp_m * 64 + mi * 16 + g;
            float2 v0 = make_float2(acc[mi][ni][0], acc[mi][ni][1]);
            float2 v1 = make_float2(acc[mi][ni][2], acc[mi][ni][3]);
            *reinterpret_cast<float2*>(out + (size_t)row0 * H_DIM + col) = v0;
            *reinterpret_cast<float2*>(out + (size_t)(row0 + 8) * H_DIM + col) = v1;
        }
}

// ---------------- prep kernels ----------------------------------------------
__global__ void conv_hidden_k(const float* __restrict__ in, __half* __restrict__ o)
{
    size_t i = (size_t)blockIdx.x * blockDim.x + threadIdx.x;
    float4 v = reinterpret_cast<const float4*>(in)[i];
    uint2 p;
    p.x = pk2h(v.x, v.y);
    p.y = pk2h(v.z, v.w);
    reinterpret_cast<uint2*>(o)[i] = p;
}

__global__ void transpose_conv_k(const float* __restrict__ in,
                                 __half* __restrict__ o, int R, int C)
{
    __shared__ float t[32][33];
    int bx = blockIdx.x * 32, by = blockIdx.y * 32;
    int tx = threadIdx.x, ty = threadIdx.y;
#pragma unroll
    for (int j = 0; j < 32; j += 8)
        t[ty + j][tx] = in[(size_t)(by + ty + j) * C + bx + tx];
    __syncthreads();
#pragma unroll
    for (int j = 0; j < 32; j += 8) {
        float a = t[tx][ty + j];
        o[(size_t)(bx + ty + j) * R + by + tx] = __float2half_rn(a);
    }
}

// ---------------- host ------------------------------------------------------
extern "C" void kernel_launch(void* const* d_in, const int* in_sizes, int n_in,
                              void* d_out, int out_size)
{
    const float* hidden = (const float*)d_in[0];   // [T, H]
    const float* wgu    = (const float*)d_in[1];   // [H, 2I]
    const float* wd     = (const float*)d_in[2];   // [I, H]
    float* out = (float*)d_out;                    // [T, H]

    __half *Ah, *W, *D, *X;
    cudaGetSymbolAddress((void**)&Ah, g_Ah);
    cudaGetSymbolAddress((void**)&W,  g_Wgu);
    cudaGetSymbolAddress((void**)&D,  g_Wd);
    cudaGetSymbolAddress((void**)&X,  g_X);

    cudaFuncSetAttribute(gemm1_k, cudaFuncAttributeMaxDynamicSharedMemorySize, SMEM_BYTES);
    cudaFuncSetAttribute(gemm2_k, cudaFuncAttributeMaxDynamicSharedMemorySize, SMEM_BYTES);

    conv_hidden_k<<<(int)(((size_t)T_TOK * H_DIM / 4) / 256), 256>>>(hidden, Ah);
    transpose_conv_k<<<dim3(2 * I_DIM / 32, H_DIM / 32), dim3(32, 8)>>>(wgu, W, H_DIM, 2 * I_DIM);
    transpose_conv_k<<<dim3(H_DIM / 32, I_DIM / 32), dim3(32, 8)>>>(wd, D, I_DIM, H_DIM);

    gemm1_k<<<dim3(I_DIM / 64, T_TOK / 128), 128, SMEM_BYTES>>>(Ah, W, X);
    gemm2_k<<<dim3(H_DIM / 128, T_TOK / 128), 128, SMEM_BYTES>>>(X, D, out);
}

// round 16
// speedup vs baseline: 1.1135x; 1.1135x over previous
#include <cuda_runtime.h>
#include <cuda_fp16.h>
#include <cstdint>

#define T_TOK 32768
#define H_DIM 2048
#define I_DIM 768

// ---------------- static device scratch (fp16) ------------------------------
__device__ __half g_Ah[(size_t)T_TOK * H_DIM];          // hidden   [T,H]
__device__ __half g_Wgu[(size_t)2 * I_DIM * H_DIM];     // w_gate_up^T [2I,H]
__device__ __half g_Wd[(size_t)H_DIM * I_DIM];          // w_down^T    [H,I]
__device__ __half g_X[(size_t)T_TOK * I_DIM];           // silu(g)*u   [T,I]

// ---------------- helpers ----------------------------------------------------
__device__ __forceinline__ uint32_t smem_u32(const void* p) {
    return (uint32_t)__cvta_generic_to_shared(p);
}
__device__ __forceinline__ void cp16(uint32_t dst, const void* src) {
    asm volatile("cp.async.cg.shared.global [%0], [%1], 16;" :: "r"(dst), "l"(src));
}
__device__ __forceinline__ void cp_commit() {
    asm volatile("cp.async.commit_group;" ::: "memory");
}
template <int N>
__device__ __forceinline__ void cp_wait() {
    asm volatile("cp.async.wait_group %0;" :: "n"(N) : "memory");
}
__device__ __forceinline__ void ldsm_x4(uint32_t* r, uint32_t addr) {
    asm volatile("ldmatrix.sync.aligned.m8n8.x4.shared.b16 {%0,%1,%2,%3}, [%4];"
                 : "=r"(r[0]), "=r"(r[1]), "=r"(r[2]), "=r"(r[3]) : "r"(addr));
}
__device__ __forceinline__ void mma16816(float* d, const uint32_t* a,
                                         uint32_t b0, uint32_t b1) {
    asm volatile(
        "mma.sync.aligned.m16n8k16.row.col.f32.f16.f16.f32 "
        "{%0,%1,%2,%3}, {%4,%5,%6,%7}, {%8,%9}, {%0,%1,%2,%3};"
        : "+f"(d[0]), "+f"(d[1]), "+f"(d[2]), "+f"(d[3])
        : "r"(a[0]), "r"(a[1]), "r"(a[2]), "r"(a[3]), "r"(b0), "r"(b1));
}
__device__ __forceinline__ uint32_t pk2h(float a, float b) {
    __half2 t = __floats2half2_rn(a, b);
    return *reinterpret_cast<uint32_t*>(&t);
}

// ======================= GEMM1 layout (BK=32, R14-proven) ====================
// rows of 32 fp16 = 64B data + 16B pad -> stride 80B; bank starts conflict-free
#define ROWB        80
#define B_OFF       10240
#define STAGE_BYTES 20480
#define NSTAGE      5
#define PFD         4
#define SMEM_BYTES  (NSTAGE * STAGE_BYTES)

__device__ __forceinline__ void load_frags(
    uint32_t SB, int ks, int warp_m, int warp_n,
    int arow, int acol, int brow, int bcol,
    uint32_t af[4][4], uint32_t bf[16])
{
#pragma unroll
    for (int bq = 0; bq < 4; bq++) {
        uint32_t rb = SB + B_OFF + (warp_n * 64 + bq * 16 + brow) * ROWB
                    + ks * 32 + bcol;
        ldsm_x4(&bf[bq * 4], rb);
    }
#pragma unroll
    for (int mi = 0; mi < 4; mi++) {
        uint32_t ra = SB + (warp_m * 64 + mi * 16 + arow) * ROWB + ks * 32 + acol;
        ldsm_x4(af[mi], ra);
    }
}

__device__ __forceinline__ void g1_load_stage(
    uint32_t SB, int k0, int bm, int nt,
    const __half* __restrict__ A, const __half* __restrict__ W, int tid)
{
#pragma unroll
    for (int c = tid; c < 512; c += 128) {            // A: 128 rows x 4 x 16B
        int row = c >> 2, kc = c & 3;
        cp16(SB + row * ROWB + kc * 16,
             A + (size_t)(bm + row) * H_DIM + k0 + kc * 8);
    }
#pragma unroll
    for (int c = tid; c < 512; c += 128) {            // B: interleaved gate/up
        int row = c >> 2, kc = c & 3;
        int wn = row >> 6, r = row & 63;
        int gr = (r < 32) ? (nt * 64 + wn * 32 + r)
                          : (I_DIM + nt * 64 + wn * 32 + r - 32);
        cp16(SB + B_OFF + row * ROWB + kc * 16,
             W + (size_t)gr * H_DIM + k0 + kc * 8);
    }
}

__global__ __launch_bounds__(128, 2)
void gemm1_k(const __half* __restrict__ A, const __half* __restrict__ W,
             __half* __restrict__ X)
{
    extern __shared__ char smem[];
    const uint32_t sb = smem_u32(smem);
    const int tid = threadIdx.x, wid = tid >> 5, lane = tid & 31;
    const int warp_m = wid & 1, warp_n = wid >> 1;
    const int nt = blockIdx.x;                  // 0..11
    const int bm = blockIdx.y * 128;
    const int NITER = H_DIM / 32;               // 64

    float acc[4][8][4];                         // ni 0..3 gate, 4..7 up
#pragma unroll
    for (int mi = 0; mi < 4; mi++)
#pragma unroll
        for (int ni = 0; ni < 8; ni++)
#pragma unroll
            for (int v = 0; v < 4; v++) acc[mi][ni][v] = 0.f;

#pragma unroll
    for (int p = 0; p < PFD; p++) {
        g1_load_stage(sb + p * STAGE_BYTES, p * 32, bm, nt, A, W, tid);
        cp_commit();
    }

    const int arow = lane & 15;
    const int acol = (lane >> 4) * 16;
    const int brow = (lane & 7) + ((lane >> 4) << 3);
    const int bcol = ((lane >> 3) & 1) * 16;

    uint32_t af0[4][4], bf0[16], af1[4][4], bf1[16];

    cp_wait<PFD - 1>();
    __syncthreads();
    load_frags(sb, 0, warp_m, warp_n, arow, acol, brow, bcol, af0, bf0);

    int s_it = 0, s_nx = PFD % NSTAGE;
    for (int it = 0; it < NITER; ++it) {
        uint32_t SBc = sb + s_it * STAGE_BYTES;
        int s_n1 = (s_it == NSTAGE - 1) ? 0 : s_it + 1;
        uint32_t SBn = sb + s_n1 * STAGE_BYTES;

        if (it + PFD < NITER) {
            g1_load_stage(sb + s_nx * STAGE_BYTES, (it + PFD) * 32, bm, nt, A, W, tid);
        }
        cp_commit();

        load_frags(SBc, 1, warp_m, warp_n, arow, acol, brow, bcol, af1, bf1);

#pragma unroll
        for (int mi = 0; mi < 4; mi++)
#pragma unroll
            for (int ni = 0; ni < 8; ni++)
                mma16816(acc[mi][ni], af0[mi], bf0[ni * 2], bf0[ni * 2 + 1]);

        cp_wait<PFD - 1>();
        __syncthreads();
        if (it + 1 < NITER) {
            load_frags(SBn, 0, warp_m, warp_n, arow, acol, brow, bcol, af0, bf0);
        }

#pragma unroll
        for (int mi = 0; mi < 4; mi++)
#pragma unroll
            for (int ni = 0; ni < 8; ni++)
                mma16816(acc[mi][ni], af1[mi], bf1[ni * 2], bf1[ni * 2 + 1]);

        s_it = s_n1;
        s_nx = (s_nx == NSTAGE - 1) ? 0 : s_nx + 1;
    }

    // epilogue: silu(gate)*up -> fp16 X
    const int g = lane >> 2, t = lane & 3;
#pragma unroll
    for (int mi = 0; mi < 4; mi++)
#pragma unroll
        for (int ni = 0; ni < 4; ni++) {
            int col = nt * 64 + warp_n * 32 + ni * 8 + t * 2;
            int row0 = bm + warp_m * 64 + mi * 16 + g;
#pragma unroll
            for (int h = 0; h < 2; h++) {
                int row = row0 + h * 8;
                float g0 = acc[mi][ni][h*2],     g1 = acc[mi][ni][h*2+1];
                float u0 = acc[mi][ni+4][h*2],   u1 = acc[mi][ni+4][h*2+1];
                float x0 = u0 * g0 / (1.0f + __expf(-g0));
                float x1 = u1 * g1 / (1.0f + __expf(-g1));
                *reinterpret_cast<uint32_t*>(X + (size_t)row * I_DIM + col) = pk2h(x0, x1);
            }
        }
}

// ======================= GEMM2 (BK=64, 3-stage ring) =========================
// rows of 64 fp16 = 128B data + 16B pad -> stride 144B (36 words);
// 8-row ldmatrix bank starts (r*36)%32 = {0,4,...,28}: conflict-free.
#define ROWB2        144
#define B_OFF2       18432
#define STAGE2_BYTES 36864
#define NSTAGE2      3
#define SMEM2_BYTES  (NSTAGE2 * STAGE2_BYTES)

__device__ __forceinline__ void load_frags2(
    uint32_t SB, int ks, int warp_m, int warp_n,
    int arow, int acol, int brow, int bcol,
    uint32_t af[4][4], uint32_t bf[16])
{
#pragma unroll
    for (int bq = 0; bq < 4; bq++) {
        uint32_t rb = SB + B_OFF2 + (warp_n * 64 + bq * 16 + brow) * ROWB2
                    + ks * 32 + bcol;
        ldsm_x4(&bf[bq * 4], rb);
    }
#pragma unroll
    for (int mi = 0; mi < 4; mi++) {
        uint32_t ra = SB + (warp_m * 64 + mi * 16 + arow) * ROWB2 + ks * 32 + acol;
        ldsm_x4(af[mi], ra);
    }
}

__device__ __forceinline__ void g2_load_stage(
    uint32_t SB, int k0, int bm, int bn,
    const __half* __restrict__ X, const __half* __restrict__ D, int tid)
{
#pragma unroll
    for (int c = tid; c < 1024; c += 128) {           // A: 128 rows x 8 x 16B
        int row = c >> 3, kc = c & 7;
        cp16(SB + row * ROWB2 + kc * 16,
             X + (size_t)(bm + row) * I_DIM + k0 + kc * 8);
    }
#pragma unroll
    for (int c = tid; c < 1024; c += 128) {
        int row = c >> 3, kc = c & 7;
        cp16(SB + B_OFF2 + row * ROWB2 + kc * 16,
             D + (size_t)(bn + row) * I_DIM + k0 + kc * 8);
    }
}

__global__ __launch_bounds__(128, 2)
void gemm2_k(const __half* __restrict__ X, const __half* __restrict__ D,
             float* __restrict__ out)
{
    extern __shared__ char smem[];
    const uint32_t sb = smem_u32(smem);
    const int tid = threadIdx.x, wid = tid >> 5, lane = tid & 31;
    const int warp_m = wid & 1, warp_n = wid >> 1;
    const int bn = blockIdx.x * 128;
    const int bm = blockIdx.y * 128;
    const int NITER = I_DIM / 64;               // 12

    float acc[4][8][4];
#pragma unroll
    for (int mi = 0; mi < 4; mi++)
#pragma unroll
        for (int ni = 0; ni < 8; ni++)
#pragma unroll
            for (int v = 0; v < 4; v++) acc[mi][ni][v] = 0.f;

    // prologue: 2 stages
    g2_load_stage(sb, 0, bm, bn, X, D, tid); cp_commit();
    g2_load_stage(sb + STAGE2_BYTES, 64, bm, bn, X, D, tid); cp_commit();

    const int arow = lane & 15;
    const int acol = (lane >> 4) * 16;
    const int brow = (lane & 7) + ((lane >> 4) << 3);
    const int bcol = ((lane >> 3) & 1) * 16;

    uint32_t afA[4][4], bfA[16], afB[4][4], bfB[16];

    cp_wait<1>();          // stage 0 complete
    __syncthreads();
    load_frags2(sb, 0, warp_m, warp_n, arow, acol, brow, bcol, afA, bfA);

    int s0 = 0;
    for (int it = 0; it < NITER; ++it) {
        const int s1 = (s0 + 1 < NSTAGE2) ? s0 + 1 : 0;
        const int s2 = (s0 + 2 < NSTAGE2) ? s0 + 2 : s0 + 2 - NSTAGE2;
        const uint32_t SB0 = sb + s0 * STAGE2_BYTES;
        const uint32_t SB1 = sb + s1 * STAGE2_BYTES;

        // prefetch stage it+2 (its last read was pre-barrier of it-1)
        if (it + 2 < NITER)
            g2_load_stage(sb + s2 * STAGE2_BYTES, (it + 2) * 64, bm, bn, X, D, tid);
        cp_commit();

        // ks1
        load_frags2(SB0, 1, warp_m, warp_n, arow, acol, brow, bcol, afB, bfB);
#pragma unroll
        for (int mi = 0; mi < 4; mi++)
#pragma unroll
            for (int ni = 0; ni < 8; ni++)
                mma16816(acc[mi][ni], afA[mi], bfA[ni * 2], bfA[ni * 2 + 1]);

        // ks2
        load_frags2(SB0, 2, warp_m, warp_n, arow, acol, brow, bcol, afA, bfA);
#pragma unroll
        for (int mi = 0; mi < 4; mi++)
#pragma unroll
            for (int ni = 0; ni < 8; ni++)
                mma16816(acc[mi][ni], afB[mi], bfB[ni * 2], bfB[ni * 2 + 1]);

        // ks3
        load_frags2(SB0, 3, warp_m, warp_n, arow, acol, brow, bcol, afB, bfB);
#pragma unroll
        for (int mi = 0; mi < 4; mi++)
#pragma unroll
            for (int ni = 0; ni < 8; ni++)
                mma16816(acc[mi][ni], afA[mi], bfA[ni * 2], bfA[ni * 2 + 1]);

        // stage s1 complete + visible to all threads, then cross-stage ks0
        cp_wait<1>();
        __syncthreads();
        if (it + 1 < NITER)
            load_frags2(SB1, 0, warp_m, warp_n, arow, acol, brow, bcol, afA, bfA);

#pragma unroll
        for (int mi = 0; mi < 4; mi++)
#pragma unroll
            for (int ni = 0; ni < 8; ni++)
                mma16816(acc[mi][ni], afB[mi], bfB[ni * 2], bfB[ni * 2 + 1]);

        s0 = s1;
    }

    const int g = lane >> 2, t = lane & 3;
#pragma unroll
    for (int mi = 0; mi < 4; mi++)
#pragma unroll
        for (int ni = 0; ni < 8; ni++) {
            int col = bn + warp_n * 64 + ni * 8 + t * 2;
            int row0 = bm + warp_m * 64 + mi * 16 + g;
            float2 v0 = make_float2(acc[mi][ni][0], acc[mi][ni][1]);
            float2 v1 = make_float2(acc[mi][ni][2], acc[mi][ni][3]);
            *reinterpret_cast<float2*>(out + (size_t)row0 * H_DIM + col) = v0;
            *reinterpret_cast<float2*>(out + (size_t)(row0 + 8) * H_DIM + col) = v1;
        }
}

// ---------------- prep kernels ----------------------------------------------
__global__ void conv_hidden_k(const float* __restrict__ in, __half* __restrict__ o)
{
    size_t i = (size_t)blockIdx.x * blockDim.x + threadIdx.x;
    float4 v = reinterpret_cast<const float4*>(in)[i];
    uint2 p;
    p.x = pk2h(v.x, v.y);
    p.y = pk2h(v.z, v.w);
    reinterpret_cast<uint2*>(o)[i] = p;
}

__global__ void transpose_conv_k(const float* __restrict__ in,
                                 __half* __restrict__ o, int R, int C)
{
    __shared__ float t[32][33];
    int bx = blockIdx.x * 32, by = blockIdx.y * 32;
    int tx = threadIdx.x, ty = threadIdx.y;
#pragma unroll
    for (int j = 0; j < 32; j += 8)
        t[ty + j][tx] = in[(size_t)(by + ty + j) * C + bx + tx];
    __syncthreads();
#pragma unroll
    for (int j = 0; j < 32; j += 8) {
        float a = t[tx][ty + j];
        o[(size_t)(bx + ty + j) * R + by + tx] = __float2half_rn(a);
    }
}

// ---------------- host ------------------------------------------------------
extern "C" void kernel_launch(void* const* d_in, const int* in_sizes, int n_in,
                              void* d_out, int out_size)
{
    const float* hidden = (const float*)d_in[0];   // [T, H]
    const float* wgu    = (const float*)d_in[1];   // [H, 2I]
    const float* wd     = (const float*)d_in[2];   // [I, H]
    float* out = (float*)d_out;                    // [T, H]

    __half *Ah, *W, *D, *X;
    cudaGetSymbolAddress((void**)&Ah, g_Ah);
    cudaGetSymbolAddress((void**)&W,  g_Wgu);
    cudaGetSymbolAddress((void**)&D,  g_Wd);
    cudaGetSymbolAddress((void**)&X,  g_X);

    cudaFuncSetAttribute(gemm1_k, cudaFuncAttributeMaxDynamicSharedMemorySize, SMEM_BYTES);
    cudaFuncSetAttribute(gemm2_k, cudaFuncAttributeMaxDynamicSharedMemorySize, SMEM2_BYTES);

    conv_hidden_k<<<(int)(((size_t)T_TOK * H_DIM / 4) / 256), 256>>>(hidden, Ah);
    transpose_conv_k<<<dim3(2 * I_DIM / 32, H_DIM / 32), dim3(32, 8)>>>(wgu, W, H_DIM, 2 * I_DIM);
    transpose_conv_k<<<dim3(H_DIM / 32, I_DIM / 32), dim3(32, 8)>>>(wd, D, I_DIM, H_DIM);

    gemm1_k<<<dim3(I_DIM / 64, T_TOK / 128), 128, SMEM_BYTES>>>(Ah, W, X);
    gemm2_k<<<dim3(H_DIM / 128, T_TOK / 128), 128, SMEM2_BYTES>>>(X, D, out);
}

// round 17
// speedup vs baseline: 1.1357x; 1.0199x over previous
#include <cuda_runtime.h>
#include <cuda_fp16.h>
#include <cstdint>

#define T_TOK 32768
#define H_DIM 2048
#define I_DIM 768

// ---------------- static device scratch (fp16) ------------------------------
__device__ __half g_Ah[(size_t)T_TOK * H_DIM];          // hidden   [T,H]
__device__ __half g_Wgu[(size_t)2 * I_DIM * H_DIM];     // w_gate_up^T [2I,H]
__device__ __half g_Wd[(size_t)H_DIM * I_DIM];          // w_down^T    [H,I]
__device__ __half g_X[(size_t)T_TOK * I_DIM];           // silu(g)*u   [T,I]

// ---------------- helpers ----------------------------------------------------
__device__ __forceinline__ uint32_t smem_u32(const void* p) {
    return (uint32_t)__cvta_generic_to_shared(p);
}
__device__ __forceinline__ void cp16(uint32_t dst, const void* src) {
    asm volatile("cp.async.cg.shared.global [%0], [%1], 16;" :: "r"(dst), "l"(src));
}
__device__ __forceinline__ void cp_commit() {
    asm volatile("cp.async.commit_group;" ::: "memory");
}
template <int N>
__device__ __forceinline__ void cp_wait() {
    asm volatile("cp.async.wait_group %0;" :: "n"(N) : "memory");
}
__device__ __forceinline__ void ldsm_x4(uint32_t* r, uint32_t addr) {
    asm volatile("ldmatrix.sync.aligned.m8n8.x4.shared.b16 {%0,%1,%2,%3}, [%4];"
                 : "=r"(r[0]), "=r"(r[1]), "=r"(r[2]), "=r"(r[3]) : "r"(addr));
}
__device__ __forceinline__ void mma16816(float* d, const uint32_t* a,
                                         uint32_t b0, uint32_t b1) {
    asm volatile(
        "mma.sync.aligned.m16n8k16.row.col.f32.f16.f16.f32 "
        "{%0,%1,%2,%3}, {%4,%5,%6,%7}, {%8,%9}, {%0,%1,%2,%3};"
        : "+f"(d[0]), "+f"(d[1]), "+f"(d[2]), "+f"(d[3])
        : "r"(a[0]), "r"(a[1]), "r"(a[2]), "r"(a[3]), "r"(b0), "r"(b1));
}
__device__ __forceinline__ uint32_t pk2h(float a, float b) {
    __half2 t = __floats2half2_rn(a, b);
    return *reinterpret_cast<uint32_t*>(&t);
}

// ============ shared BK=64 layout (both GEMMs) ============
// rows of 64 fp16 = 128B data + 16B pad -> stride 144B (36 words);
// 8-row ldmatrix bank starts (r*36)%32 = {0,4,...,28}: conflict-free.
#define ROWB2        144
#define B_OFF2       18432
#define STAGE2_BYTES 36864
#define NSTAGE2      3
#define SMEM2_BYTES  (NSTAGE2 * STAGE2_BYTES)

__device__ __forceinline__ void load_frags2(
    uint32_t SB, int ks, int warp_m, int warp_n,
    int arow, int acol, int brow, int bcol,
    uint32_t af[4][4], uint32_t bf[16])
{
#pragma unroll
    for (int bq = 0; bq < 4; bq++) {
        uint32_t rb = SB + B_OFF2 + (warp_n * 64 + bq * 16 + brow) * ROWB2
                    + ks * 32 + bcol;
        ldsm_x4(&bf[bq * 4], rb);
    }
#pragma unroll
    for (int mi = 0; mi < 4; mi++) {
        uint32_t ra = SB + (warp_m * 64 + mi * 16 + arow) * ROWB2 + ks * 32 + acol;
        ldsm_x4(af[mi], ra);
    }
}

// ============================================================================
// GEMM1: hidden[T,H] x Wgu^T[2I,H] -> silu(gate)*up -> X[T,I] fp16
// CTA: 128 thr, 4 warps (2m x 2n). Tile 128x64(g+u). Warp tile 64x64.
// BK=64, 3-stage ring, ONE barrier per 128 MMAs (gemm2-R16-proven structure).
// B rows interleaved: per 64-row warp_n chunk = [32 gate | 32 up].
// ============================================================================
__device__ __forceinline__ void g1_load_stage(
    uint32_t SB, int k0, int bm, int nt,
    const __half* __restrict__ A, const __half* __restrict__ W, int tid)
{
#pragma unroll
    for (int c = tid; c < 1024; c += 128) {           // A: 128 rows x 8 x 16B
        int row = c >> 3, kc = c & 7;
        cp16(SB + row * ROWB2 + kc * 16,
             A + (size_t)(bm + row) * H_DIM + k0 + kc * 8);
    }
#pragma unroll
    for (int c = tid; c < 1024; c += 128) {           // B: interleaved gate/up
        int row = c >> 3, kc = c & 7;
        int wn = row >> 6, r = row & 63;
        int gr = (r < 32) ? (nt * 64 + wn * 32 + r)
                          : (I_DIM + nt * 64 + wn * 32 + r - 32);
        cp16(SB + B_OFF2 + row * ROWB2 + kc * 16,
             W + (size_t)gr * H_DIM + k0 + kc * 8);
    }
}

__global__ __launch_bounds__(128, 2)
void gemm1_k(const __half* __restrict__ A, const __half* __restrict__ W,
             __half* __restrict__ X)
{
    extern __shared__ char smem[];
    const uint32_t sb = smem_u32(smem);
    const int tid = threadIdx.x, wid = tid >> 5, lane = tid & 31;
    const int warp_m = wid & 1, warp_n = wid >> 1;
    const int nt = blockIdx.x;                  // 0..11
    const int bm = blockIdx.y * 128;
    const int NITER = H_DIM / 64;               // 32

    float acc[4][8][4];                         // ni 0..3 gate, 4..7 up
#pragma unroll
    for (int mi = 0; mi < 4; mi++)
#pragma unroll
        for (int ni = 0; ni < 8; ni++)
#pragma unroll
            for (int v = 0; v < 4; v++) acc[mi][ni][v] = 0.f;

    g1_load_stage(sb, 0, bm, nt, A, W, tid); cp_commit();
    g1_load_stage(sb + STAGE2_BYTES, 64, bm, nt, A, W, tid); cp_commit();

    const int arow = lane & 15;
    const int acol = (lane >> 4) * 16;
    const int brow = (lane & 7) + ((lane >> 4) << 3);
    const int bcol = ((lane >> 3) & 1) * 16;

    uint32_t afA[4][4], bfA[16], afB[4][4], bfB[16];

    cp_wait<1>();
    __syncthreads();
    load_frags2(sb, 0, warp_m, warp_n, arow, acol, brow, bcol, afA, bfA);

    int s0 = 0;
    for (int it = 0; it < NITER; ++it) {
        const int s1 = (s0 + 1 < NSTAGE2) ? s0 + 1 : 0;
        const int s2 = (s0 + 2 < NSTAGE2) ? s0 + 2 : s0 + 2 - NSTAGE2;
        const uint32_t SB0 = sb + s0 * STAGE2_BYTES;
        const uint32_t SB1 = sb + s1 * STAGE2_BYTES;

        if (it + 2 < NITER)
            g1_load_stage(sb + s2 * STAGE2_BYTES, (it + 2) * 64, bm, nt, A, W, tid);
        cp_commit();

        // ks1
        load_frags2(SB0, 1, warp_m, warp_n, arow, acol, brow, bcol, afB, bfB);
#pragma unroll
        for (int mi = 0; mi < 4; mi++)
#pragma unroll
            for (int ni = 0; ni < 8; ni++)
                mma16816(acc[mi][ni], afA[mi], bfA[ni * 2], bfA[ni * 2 + 1]);

        // ks2
        load_frags2(SB0, 2, warp_m, warp_n, arow, acol, brow, bcol, afA, bfA);
#pragma unroll
        for (int mi = 0; mi < 4; mi++)
#pragma unroll
            for (int ni = 0; ni < 8; ni++)
                mma16816(acc[mi][ni], afB[mi], bfB[ni * 2], bfB[ni * 2 + 1]);

        // ks3
        load_frags2(SB0, 3, warp_m, warp_n, arow, acol, brow, bcol, afB, bfB);
#pragma unroll
        for (int mi = 0; mi < 4; mi++)
#pragma unroll
            for (int ni = 0; ni < 8; ni++)
                mma16816(acc[mi][ni], afA[mi], bfA[ni * 2], bfA[ni * 2 + 1]);

        // stage s1 complete + visible, then cross-stage ks0
        cp_wait<1>();
        __syncthreads();
        if (it + 1 < NITER)
            load_frags2(SB1, 0, warp_m, warp_n, arow, acol, brow, bcol, afA, bfA);

#pragma unroll
        for (int mi = 0; mi < 4; mi++)
#pragma unroll
            for (int ni = 0; ni < 8; ni++)
                mma16816(acc[mi][ni], afB[mi], bfB[ni * 2], bfB[ni * 2 + 1]);

        s0 = s1;
    }

    // epilogue: silu(gate)*up -> fp16 X (gate=acc[ni], up=acc[ni+4])
    const int g = lane >> 2, t = lane & 3;
#pragma unroll
    for (int mi = 0; mi < 4; mi++)
#pragma unroll
        for (int ni = 0; ni < 4; ni++) {
            int col = nt * 64 + warp_n * 32 + ni * 8 + t * 2;
            int row0 = bm + warp_m * 64 + mi * 16 + g;
#pragma unroll
            for (int h = 0; h < 2; h++) {
                int row = row0 + h * 8;
                float g0 = acc[mi][ni][h*2],     g1 = acc[mi][ni][h*2+1];
                float u0 = acc[mi][ni+4][h*2],   u1 = acc[mi][ni+4][h*2+1];
                float x0 = u0 * g0 / (1.0f + __expf(-g0));
                float x1 = u1 * g1 / (1.0f + __expf(-g1));
                *reinterpret_cast<uint32_t*>(X + (size_t)row * I_DIM + col) = pk2h(x0, x1);
            }
        }
}

// ============================================================================
// GEMM2: X[T,I] x Wd^T[H,I] -> out[T,H] fp32  (unchanged from R16)
// ============================================================================
__device__ __forceinline__ void g2_load_stage(
    uint32_t SB, int k0, int bm, int bn,
    const __half* __restrict__ X, const __half* __restrict__ D, int tid)
{
#pragma unroll
    for (int c = tid; c < 1024; c += 128) {
        int row = c >> 3, kc = c & 7;
        cp16(SB + row * ROWB2 + kc * 16,
             X + (size_t)(bm + row) * I_DIM + k0 + kc * 8);
    }
#pragma unroll
    for (int c = tid; c < 1024; c += 128) {
        int row = c >> 3, kc = c & 7;
        cp16(SB + B_OFF2 + row * ROWB2 + kc * 16,
             D + (size_t)(bn + row) * I_DIM + k0 + kc * 8);
    }
}

__global__ __launch_bounds__(128, 2)
void gemm2_k(const __half* __restrict__ X, const __half* __restrict__ D,
             float* __restrict__ out)
{
    extern __shared__ char smem[];
    const uint32_t sb = smem_u32(smem);
    const int tid = threadIdx.x, wid = tid >> 5, lane = tid & 31;
    const int warp_m = wid & 1, warp_n = wid >> 1;
    const int bn = blockIdx.x * 128;
    const int bm = blockIdx.y * 128;
    const int NITER = I_DIM / 64;               // 12

    float acc[4][8][4];
#pragma unroll
    for (int mi = 0; mi < 4; mi++)
#pragma unroll
        for (int ni = 0; ni < 8; ni++)
#pragma unroll
            for (int v = 0; v < 4; v++) acc[mi][ni][v] = 0.f;

    g2_load_stage(sb, 0, bm, bn, X, D, tid); cp_commit();
    g2_load_stage(sb + STAGE2_BYTES, 64, bm, bn, X, D, tid); cp_commit();

    const int arow = lane & 15;
    const int acol = (lane >> 4) * 16;
    const int brow = (lane & 7) + ((lane >> 4) << 3);
    const int bcol = ((lane >> 3) & 1) * 16;

    uint32_t afA[4][4], bfA[16], afB[4][4], bfB[16];

    cp_wait<1>();
    __syncthreads();
    load_frags2(sb, 0, warp_m, warp_n, arow, acol, brow, bcol, afA, bfA);

    int s0 = 0;
    for (int it = 0; it < NITER; ++it) {
        const int s1 = (s0 + 1 < NSTAGE2) ? s0 + 1 : 0;
        const int s2 = (s0 + 2 < NSTAGE2) ? s0 + 2 : s0 + 2 - NSTAGE2;
        const uint32_t SB0 = sb + s0 * STAGE2_BYTES;
        const uint32_t SB1 = sb + s1 * STAGE2_BYTES;

        if (it + 2 < NITER)
            g2_load_stage(sb + s2 * STAGE2_BYTES, (it + 2) * 64, bm, bn, X, D, tid);
        cp_commit();

        load_frags2(SB0, 1, warp_m, warp_n, arow, acol, brow, bcol, afB, bfB);
#pragma unroll
        for (int mi = 0; mi < 4; mi++)
#pragma unroll
            for (int ni = 0; ni < 8; ni++)
                mma16816(acc[mi][ni], afA[mi], bfA[ni * 2], bfA[ni * 2 + 1]);

        load_frags2(SB0, 2, warp_m, warp_n, arow, acol, brow, bcol, afA, bfA);
#pragma unroll
        for (int mi = 0; mi < 4; mi++)
#pragma unroll
            for (int ni = 0; ni < 8; ni++)
                mma16816(acc[mi][ni], afB[mi], bfB[ni * 2], bfB[ni * 2 + 1]);

        load_frags2(SB0, 3, warp_m, warp_n, arow, acol, brow, bcol, afB, bfB);
#pragma unroll
        for (int mi = 0; mi < 4; mi++)
#pragma unroll
            for (int ni = 0; ni < 8; ni++)
                mma16816(acc[mi][ni], afA[mi], bfA[ni * 2], bfA[ni * 2 + 1]);

        cp_wait<1>();
        __syncthreads();
        if (it + 1 < NITER)
            load_frags2(SB1, 0, warp_m, warp_n, arow, acol, brow, bcol, afA, bfA);

#pragma unroll
        for (int mi = 0; mi < 4; mi++)
#pragma unroll
            for (int ni = 0; ni < 8; ni++)
                mma16816(acc[mi][ni], afB[mi], bfB[ni * 2], bfB[ni * 2 + 1]);

        s0 = s1;
    }

    const int g = lane >> 2, t = lane & 3;
#pragma unroll
    for (int mi = 0; mi < 4; mi++)
#pragma unroll
        for (int ni = 0; ni < 8; ni++) {
            int col = bn + warp_n * 64 + ni * 8 + t * 2;
            int row0 = bm + warp_m * 64 + mi * 16 + g;
            float2 v0 = make_float2(acc[mi][ni][0], acc[mi][ni][1]);
            float2 v1 = make_float2(acc[mi][ni][2], acc[mi][ni][3]);
            *reinterpret_cast<float2*>(out + (size_t)row0 * H_DIM + col) = v0;
            *reinterpret_cast<float2*>(out + (size_t)(row0 + 8) * H_DIM + col) = v1;
        }
}

// ---------------- prep kernels ----------------------------------------------
__global__ void conv_hidden_k(const float* __restrict__ in, __half* __restrict__ o)
{
    size_t i = (size_t)blockIdx.x * blockDim.x + threadIdx.x;
    float4 v = reinterpret_cast<const float4*>(in)[i];
    uint2 p;
    p.x = pk2h(v.x, v.y);
    p.y = pk2h(v.z, v.w);
    reinterpret_cast<uint2*>(o)[i] = p;
}

__global__ void transpose_conv_k(const float* __restrict__ in,
                                 __half* __restrict__ o, int R, int C)
{
    __shared__ float t[32][33];
    int bx = blockIdx.x * 32, by = blockIdx.y * 32;
    int tx = threadIdx.x, ty = threadIdx.y;
#pragma unroll
    for (int j = 0; j < 32; j += 8)
        t[ty + j][tx] = in[(size_t)(by + ty + j) * C + bx + tx];
    __syncthreads();
#pragma unroll
    for (int j = 0; j < 32; j += 8) {
        float a = t[tx][ty + j];
        o[(size_t)(bx + ty + j) * R + by + tx] = __float2half_rn(a);
    }
}

// ---------------- host ------------------------------------------------------
extern "C" void kernel_launch(void* const* d_in, const int* in_sizes, int n_in,
                              void* d_out, int out_size)
{
    const float* hidden = (const float*)d_in[0];   // [T, H]
    const float* wgu    = (const float*)d_in[1];   // [H, 2I]
    const float* wd     = (const float*)d_in[2];   // [I, H]
    float* out = (float*)d_out;                    // [T, H]

    __half *Ah, *W, *D, *X;
    cudaGetSymbolAddress((void**)&Ah, g_Ah);
    cudaGetSymbolAddress((void**)&W,  g_Wgu);
    cudaGetSymbolAddress((void**)&D,  g_Wd);
    cudaGetSymbolAddress((void**)&X,  g_X);

    cudaFuncSetAttribute(gemm1_k, cudaFuncAttributeMaxDynamicSharedMemorySize, SMEM2_BYTES);
    cudaFuncSetAttribute(gemm2_k, cudaFuncAttributeMaxDynamicSharedMemorySize, SMEM2_BYTES);

    conv_hidden_k<<<(int)(((size_t)T_TOK * H_DIM / 4) / 256), 256>>>(hidden, Ah);
    transpose_conv_k<<<dim3(2 * I_DIM / 32, H_DIM / 32), dim3(32, 8)>>>(wgu, W, H_DIM, 2 * I_DIM);
    transpose_conv_k<<<dim3(H_DIM / 32, I_DIM / 32), dim3(32, 8)>>>(wd, D, I_DIM, H_DIM);

    gemm1_k<<<dim3(I_DIM / 64, T_TOK / 128), 128, SMEM2_BYTES>>>(Ah, W, X);
    gemm2_k<<<dim3(H_DIM / 128, T_TOK / 128), 128, SMEM2_BYTES>>>(X, D, out);
}